// round 9
// baseline (speedup 1.0000x reference)
#include <cuda_runtime.h>
#include <math.h>
#include <stdint.h>

// Problem constants
#define Bsz 8192
#define Kc 32
#define Dd 256
#define TILE_B 32
#define NBLK 256
#define THREADS 512

// Shared memory layout (float offsets)
// GEMM phase:
//   aFrag [0, 8192)       : A fragments [kt 32][mt 2][lane 32][reg 4]
//   bFrag [8192, 40960)   : 2 buffers x 16384 ([ktc 4][nt 64][reg 2][lane-swz 32])
// Overlay after GEMM (PA regions are 64x256 tf32 = 16384 words EACH):
//   PA1 [0,16384)      : phase-C GEMM1 A frags (z^2 rows 0-31, q rows 32-63)
//   PA2 [16384,32768)  : phase-C GEMM2 A frags (z rows 0-31, mu rows 32-63)
//   ISCF[32768,40960)  : isc B frags [kt 32][ntc 4][reg 2][lane-swz 32]
//   MCIF[40960,49152)  : mci B frags
//   DOTS[49152,53376)  : [4 dots][32 r][33]
// Always live: reduction region at 53376+
#define OFF_AF   0
#define OFF_BF   8192
#define BUFSTR   16384
#define OFF_PA1  0
#define OFF_PA2  16384
#define OFF_ISCF 32768
#define OFF_MCIF 40960
#define OFF_DOTS 49152
#define OFF_REDP 53376
#define OFF_REDG 53888
#define OFF_C2H  53904
#define OFF_CLH  53968
#define OFF_C2F  54032
#define OFF_CLF  54064
#define OFF_FLAG 54096
#define SMEM_FLOATS 54100
#define SMEM_BYTES (SMEM_FLOATS * 4)

// Cross-block scratch
__device__ float g_gaussPart[NBLK];
__device__ float g_piPart[NBLK * Kc];
__device__ unsigned int g_count;

// ---- helpers ----
__device__ __forceinline__ uint32_t f2tf32(float f) {
    uint32_t r; asm("cvt.rna.tf32.f32 %0,%1;" : "=r"(r) : "f"(f)); return r;
}
__device__ __forceinline__ float wredsum(float v) {
#pragma unroll
    for (int o = 16; o; o >>= 1) v += __shfl_xor_sync(0xffffffffu, v, o);
    return v;
}
__device__ __forceinline__ void mma_tf32(float* d, const uint32_t* a,
                                         uint32_t b0, uint32_t b1) {
    asm volatile(
        "mma.sync.aligned.m16n8k8.row.col.f32.tf32.tf32.f32 "
        "{%0,%1,%2,%3},{%4,%5,%6,%7},{%8,%9},{%0,%1,%2,%3};"
        : "+f"(d[0]), "+f"(d[1]), "+f"(d[2]), "+f"(d[3])
        : "r"(a[0]), "r"(a[1]), "r"(a[2]), "r"(a[3]), "r"(b0), "r"(b1));
}

// ---------------------------------------------------------------------------
__global__ void __launch_bounds__(THREADS)
fused_kernel(const float* __restrict__ X, const float* __restrict__ EPS,
             const float* __restrict__ Wmu, const float* __restrict__ bmu,
             const float* __restrict__ Wsig, const float* __restrict__ bsig,
             const float* __restrict__ muc, const float* __restrict__ lsc,
             float* __restrict__ out, int out_size) {
    extern __shared__ float sm[];
    uint32_t* smU = (uint32_t*)sm;
    float* dots  = sm + OFF_DOTS;
    float* redPi = sm + OFF_REDP;
    float* redG  = sm + OFF_REDG;
    float* c2h   = sm + OFF_C2H;
    float* clh   = sm + OFF_CLH;
    float* c2f   = sm + OFF_C2F;
    float* clf   = sm + OFF_CLF;
    int*   flag  = (int*)(sm + OFF_FLAG);

    const int t = threadIdx.x;
    const int b0 = blockIdx.x * TILE_B;
    const int wi = t >> 5, lane = t & 31;
    const int g = lane >> 2, tg = lane & 3;
    const int cb = wi * 16;              // this warp's col block (0..240)

    // ============ X -> A fragments (tf32) ============
#pragma unroll
    for (int p = 0; p < 16; ++p) {
        int i = p * THREADS + t;
        int r = i >> 8, d = i & 255;
        uint32_t v = f2tf32(X[(b0 + r) * Dd + d]);
        int mt = r >> 4, rl = r & 15, gg = rl & 7, hi = rl >> 3;
        int kt = d >> 3, dc = d & 7, tgx = dc & 3, kh = dc >> 2;
        smU[OFF_AF + (((kt * 2 + mt) * 32) + gg * 4 + tgx) * 4 + (hi + 2 * kh)] = v;
    }

    // ============ W staging ============
    const int t8 = t >> 3, f4 = t & 7;
    const float4* am4 = (const float4*)Wmu  + t8 * 64 + f4;
    const float4* as4 = (const float4*)Wsig + t8 * 64 + f4;
    const int ktc_s = f4 >> 1, reg_s = f4 & 1;
    const int eg_s = t8 & 7;
    const int dstBase = ktc_s * 4096 + (t >> 6) * 64 + reg_s * 32 + ((eg_s ^ f4) * 4);

    float acc[2][2][2][4];   // [mt][mat][j][creg]
#pragma unroll
    for (int a = 0; a < 2; ++a)
#pragma unroll
        for (int b = 0; b < 2; ++b)
#pragma unroll
            for (int c = 0; c < 2; ++c)
#pragma unroll
                for (int q = 0; q < 4; ++q) acc[a][b][c][q] = 0.f;

    // stage chunk 0
    {
#pragma unroll
        for (int p = 0; p < 8; ++p) {
            float4 v = (p < 4) ? am4[p * 4096] : as4[(p - 4) * 4096];
            uint4 c = {f2tf32(v.x), f2tf32(v.y), f2tf32(v.z), f2tf32(v.w)};
            *(uint4*)&smU[OFF_BF + dstBase + p * 512] = c;
        }
    }
    __syncthreads();

    // ============ main GEMM: 8 chunks of 32 d ============
#pragma unroll 1
    for (int ch = 0; ch < 8; ++ch) {
        float4 pf[8];
        if (ch < 7) {
#pragma unroll
            for (int p = 0; p < 8; ++p)
                pf[p] = (p < 4) ? am4[p * 4096 + (ch + 1) * 8]
                                : as4[(p - 4) * 4096 + (ch + 1) * 8];
        }
        const uint32_t* bufB = smU + OFF_BF + (ch & 1) * BUFSTR;
#pragma unroll
        for (int ktc = 0; ktc < 4; ++ktc) {
            int kt = ch * 4 + ktc;
            uint32_t a0[4], a1[4];
            *(uint4*)a0 = *(const uint4*)&smU[OFF_AF + ((kt * 2 + 0) * 32 + lane) * 4];
            *(uint4*)a1 = *(const uint4*)&smU[OFF_AF + ((kt * 2 + 1) * 32 + lane) * 4];
            const int p0 = lane ^ (ktc * 8);
            const int p1 = lane ^ (ktc * 8 + 4);
#pragma unroll
            for (int m = 0; m < 2; ++m) {
#pragma unroll
                for (int j = 0; j < 2; ++j) {
                    int ntg = m * 32 + wi * 2 + j;
                    const uint32_t* base = bufB + ktc * 4096 + ntg * 64;
                    uint32_t b0r = base[p0];
                    uint32_t b1r = base[32 + p1];
                    mma_tf32(acc[0][m][j], a0, b0r, b1r);
                    mma_tf32(acc[1][m][j], a1, b0r, b1r);
                }
            }
        }
        if (ch < 7) {
            uint32_t* dstB = smU + OFF_BF + ((ch + 1) & 1) * BUFSTR + dstBase;
#pragma unroll
            for (int p = 0; p < 8; ++p) {
                uint4 c = {f2tf32(pf[p].x), f2tf32(pf[p].y), f2tf32(pf[p].z), f2tf32(pf[p].w)};
                *(uint4*)&dstB[p * 512] = c;
            }
            __syncthreads();
        }
    }
    __syncthreads();   // all fragment reads done; overlays safe

    // ============ Phase B: register epilogue -> z out + phase-C A frags ======
#pragma unroll
    for (int mt = 0; mt < 2; ++mt) {
#pragma unroll
        for (int j = 0; j < 2; ++j) {
            int e2 = cb + j * 8 + 2 * tg;
            float2 bm = *(const float2*)&bmu[e2];
            float2 bs = *(const float2*)&bsig[e2];
            int ktw = wi * 2 + j;
#pragma unroll
            for (int hi = 0; hi < 2; ++hi) {
                int r = mt * 16 + g + 8 * hi;
                int ci = hi * 2;
                float mu0 = acc[mt][0][j][ci + 0] + bm.x;
                float mu1 = acc[mt][0][j][ci + 1] + bm.y;
                float ls0 = acc[mt][1][j][ci + 0] + bs.x;
                float ls1 = acc[mt][1][j][ci + 1] + bs.y;
                float ez0 = __expf(ls0), ez1 = __expf(ls1);
                float2 ep = *(const float2*)&EPS[(b0 + r) * Dd + e2];
                float z0 = fmaf(sqrtf(ez0), ep.x, mu0);
                float z1 = fmaf(sqrtf(ez1), ep.y, mu1);
                float2 zv = {z0, z1};
                *(float2*)&out[(b0 + r) * Dd + e2] = zv;
                float q0 = fmaf(mu0, mu0, ez0);
                float q1 = fmaf(mu1, mu1, ez1);
#pragma unroll
                for (int par = 0; par < 2; ++par) {
                    int dd = 2 * tg + par;
                    int kh = dd >> 2, tgp = dd & 3;
                    int reg = hi + 2 * kh;
                    int lanep = g * 4 + tgp;
                    float zz = par ? z1 : z0;
                    float qq = par ? q1 : q0;
                    float mm = par ? mu1 : mu0;
                    int i1a = OFF_PA1 + ((ktw * 4 + mt)     * 4 + reg) * 32 + lanep;
                    int i1b = OFF_PA1 + ((ktw * 4 + mt + 2) * 4 + reg) * 32 + lanep;
                    int i2a = OFF_PA2 + ((ktw * 4 + mt)     * 4 + reg) * 32 + lanep;
                    int i2b = OFF_PA2 + ((ktw * 4 + mt + 2) * 4 + reg) * 32 + lanep;
                    smU[i1a] = f2tf32(zz * zz);
                    smU[i1b] = f2tf32(qq);
                    smU[i2a] = f2tf32(zz);
                    smU[i2b] = f2tf32(mm);
                }
            }
        }
    }

    // ============ cluster tables -> B frags (+ c2/clsc) ============
    {
        const float4* lsc4 = (const float4*)lsc;
        const float4* muc4 = (const float4*)muc;
#pragma unroll
        for (int p = 0; p < 4; ++p) {
            int j = p * THREADS + t;
            int k = j >> 6, d4 = j & 63;
            float4 l4 = lsc4[j];
            float4 m4 = muc4[j];
            float4 i4 = {__expf(-l4.x), __expf(-l4.y), __expf(-l4.z), __expf(-l4.w)};
            float4 mc = {m4.x * i4.x, m4.y * i4.y, m4.z * i4.z, m4.w * i4.w};
            int kt = d4 >> 1, reg = d4 & 1;
            int g2 = k & 7, ntc = k >> 3;
            int pos = ((kt * 4 + ntc) * 2 + reg) * 32 + ((g2 ^ (kt & 7)) * 4);
            uint4 ci = {f2tf32(i4.x), f2tf32(i4.y), f2tf32(i4.z), f2tf32(i4.w)};
            uint4 cm = {f2tf32(mc.x), f2tf32(mc.y), f2tf32(mc.z), f2tf32(mc.w)};
            *(uint4*)&smU[OFF_ISCF + pos] = ci;
            *(uint4*)&smU[OFF_MCIF + pos] = cm;
            float cp = m4.x * m4.x * i4.x + m4.y * m4.y * i4.y
                     + m4.z * m4.z * i4.z + m4.w * m4.w * i4.w;
            float cl = l4.x + l4.y + l4.z + l4.w;
            cp = wredsum(cp);
            cl = wredsum(cl);
            if (lane == 0) {
                int kk = p * 8 + (wi >> 1);
                int half = wi & 1;
                c2h[kk * 2 + half] = cp;
                clh[kk * 2 + half] = cl;
            }
        }
    }
    __syncthreads();
    if (t < 32) {
        c2f[t] = c2h[t * 2] + c2h[t * 2 + 1];
        clf[t] = clh[t * 2] + clh[t * 2 + 1];
    }
    __syncthreads();

    // ============ Phase C: two 64x32x256 GEMMs on tensor cores ============
    {
        const int mtc = wi >> 2, ntc = wi & 3;
        float dA[2][4];
#pragma unroll
        for (int s = 0; s < 2; ++s)
#pragma unroll
            for (int q = 0; q < 4; ++q) dA[s][q] = 0.f;
#pragma unroll 4
        for (int kt = 0; kt < 32; ++kt) {
            uint32_t af1[4], af2[4];
#pragma unroll
            for (int rr = 0; rr < 4; ++rr) {
                af1[rr] = smU[OFF_PA1 + ((kt * 4 + mtc) * 4 + rr) * 32 + lane];
                af2[rr] = smU[OFF_PA2 + ((kt * 4 + mtc) * 4 + rr) * 32 + lane];
            }
            int lx = lane ^ ((kt & 7) << 2);
            int bb = ((kt * 4 + ntc) * 2) * 32;
            uint32_t i0 = smU[OFF_ISCF + bb + lx];
            uint32_t i1 = smU[OFF_ISCF + bb + 32 + lx];
            uint32_t m0 = smU[OFF_MCIF + bb + lx];
            uint32_t m1 = smU[OFF_MCIF + bb + 32 + lx];
            mma_tf32(dA[0], af1, i0, i1);
            mma_tf32(dA[1], af2, m0, m1);
        }
        // scatter to dots[4][32][33]
        int dot0 = (mtc < 2) ? 0 : 2;
        int rloc = (mtc & 1) * 16 + g;
#pragma unroll
        for (int hi = 0; hi < 2; ++hi) {
#pragma unroll
            for (int par = 0; par < 2; ++par) {
                int r = rloc + 8 * hi;
                int k = ntc * 8 + 2 * tg + par;
                dots[dot0 * 1056 + r * 33 + k]       = dA[0][hi * 2 + par];
                dots[(dot0 + 1) * 1056 + r * 33 + k] = dA[1][hi * 2 + par];
            }
        }
    }
    __syncthreads();

    // ============ softmax + loss partials: warp per 2 rows, lane == k ======
    float c2v = c2f[lane], clv = clf[lane];
    float piAcc = 0.f, gAcc = 0.f;
#pragma unroll
    for (int rr = 0; rr < 2; ++rr) {
        int r = wi * 2 + rr;
        float a1 = dots[0 * 1056 + r * 33 + lane];
        float a2 = dots[1 * 1056 + r * 33 + lane];
        float a3 = dots[2 * 1056 + r * 33 + lane];
        float a4 = dots[3 * 1056 + r * 33 + lane];

        float logit = -(a1 - 2.f * a2 + c2v);
        float S = clv + a3 - 2.f * a4 + c2v;

        float mx = logit;
#pragma unroll
        for (int o = 16; o; o >>= 1) mx = fmaxf(mx, __shfl_xor_sync(0xffffffffu, mx, o));
        float p = __expf(logit - mx);
        float ssum = wredsum(p);
        float pi = p / ssum + 1e-10f;

        piAcc += pi;
        gAcc += wredsum(pi * S);
    }

    // ---- block partials ----
    redPi[wi * 32 + lane] = piAcc;
    if (lane == 0) redG[wi] = gAcc;
    __syncthreads();
    if (wi == 0) {
        float ps = 0.f;
#pragma unroll
        for (int i = 0; i < 16; ++i) ps += redPi[i * 32 + lane];
        g_piPart[blockIdx.x * 32 + lane] = ps;
        if (lane == 0) {
            float gsum = 0.f;
#pragma unroll
            for (int i = 0; i < 16; ++i) gsum += redG[i];
            g_gaussPart[blockIdx.x] = gsum;
        }
    }
    __syncthreads();

    // ---- last-block folded finalize ----
    if (t == 0) {
        __threadfence();
        unsigned int old = atomicAdd(&g_count, 1u);
        *flag = (old == NBLK - 1) ? 1 : 0;
    }
    __syncthreads();
    if (*flag) {
        if (t == 0) atomicExch(&g_count, 0u);
        __threadfence();
        if (t < 256) {
            float gg = g_gaussPart[t];
            gg = wredsum(gg);
            if (lane == 0) redG[wi] = gg;
        }
        {
            float ps = 0.f;
#pragma unroll
            for (int j = 0; j < 16; ++j)
                ps += g_piPart[(wi * 16 + j) * 32 + lane];
            redPi[wi * 32 + lane] = ps;
        }
        __syncthreads();
        if (t == 0) {
            float G = 0.f;
#pragma unroll
            for (int i = 0; i < 8; ++i) G += redG[i];
            out[out_size - 2] = 0.5f * G;
        }
        if (wi == 0) {
            float P = 0.f;
#pragma unroll
            for (int i = 0; i < 16; ++i) P += redPi[i * 32 + lane];
            float mp = P / (float)Bsz;
            float u = mp * logf(mp);
            u = wredsum(u);
            if (lane == 0) out[out_size - 1] = u / (float)Kc;
        }
    }
}

// ---------------------------------------------------------------------------
extern "C" void kernel_launch(void* const* d_in, const int* in_sizes, int n_in,
                              void* d_out, int out_size) {
    const float* X    = (const float*)d_in[0];
    const float* EPS  = (const float*)d_in[1];
    const float* Wmu  = (const float*)d_in[2];
    const float* bmu  = (const float*)d_in[3];
    const float* Wsig = (const float*)d_in[4];
    const float* bsig = (const float*)d_in[5];
    const float* muc  = (const float*)d_in[6];
    const float* lsc  = (const float*)d_in[7];
    float* out = (float*)d_out;

    static bool attr_set = false;
    if (!attr_set) {
        cudaFuncSetAttribute(fused_kernel,
                             cudaFuncAttributeMaxDynamicSharedMemorySize, SMEM_BYTES);
        attr_set = true;
    }
    fused_kernel<<<NBLK, THREADS, SMEM_BYTES>>>(X, EPS, Wmu, bmu, Wsig, bsig,
                                                muc, lsc, out, out_size);
}